// round 2
// baseline (speedup 1.0000x reference)
#include <cuda_runtime.h>

#define CCH 256
#define HH 256
#define WW 256
#define PLANE (HH * WW)
#define TH 16
#define TW 32
#define HALO_H (TH + 6)          // 22 rows
#define SMW 40                    // smem row width in floats (== halo width, 8B-aligned window)
#define SMW2 (SMW / 2)            // 20 float2 per row
#define HALO_N2 (HALO_H * SMW2)   // 440 float2 total
#define NSLOT 4
#define NTHREADS 128
#define EPSF 1e-12f

__global__ __launch_bounds__(NTHREADS, 2)
void corr_kernel(const float* __restrict__ x,
                 const float* __restrict__ y,
                 float* __restrict__ out)
{
    __shared__ __align__(16) float sy[HALO_H * SMW];

    const int tid = threadIdx.x;
    const int tx = tid & 7;        // 0..7, each owns 4 w-pixels
    const int ty = tid >> 3;       // 0..15
    const int b  = blockIdx.z;
    const int h0 = blockIdx.y * TH;
    const int w0 = blockIdx.x * TW;
    const int h  = h0 + ty;

    // ---- staging precompute: halo window gy in [h0-3, h0+18], gx in [w0-4, w0+35]
    // (even gx start -> aligned float2 global loads; pairs never straddle image edge)
    // smem float2 index == linear staging index (width == stride), so only the
    // global offset + validity need registers.
    int g2of[NSLOT];
    unsigned mask = 0;
    #pragma unroll
    for (int k = 0; k < NSLOT; k++) {
        int idx = tid + k * NTHREADS;
        int r   = idx / SMW2;
        int cc  = idx - r * SMW2;
        int gy  = h0 - 3 + r;
        int gx  = w0 - 4 + 2 * cc;
        g2of[k] = gy * (WW / 2) + (gx >> 1);
        bool wr  = idx < HALO_N2;
        bool vld = wr && gy >= 0 && gy < HH && gx >= 0 && gx < WW;
        if (wr)  mask |= 1u << k;
        if (vld) mask |= 0x100u << k;
    }

    const float4* xp = reinterpret_cast<const float4*>(
        x + (((size_t)b * CCH) * HH + h) * WW + w0 + tx * 4);
    const float2* yp = reinterpret_cast<const float2*>(y) +
        (size_t)b * CCH * (PLANE / 2);

    float acc[49][4];
    #pragma unroll
    for (int o = 0; o < 49; o++) {
        acc[o][0] = 0.f; acc[o][1] = 0.f; acc[o][2] = 0.f; acc[o][3] = 0.f;
    }
    float sxx[4] = {0.f, 0.f, 0.f, 0.f};
    float2 syy[NSLOT];
    #pragma unroll
    for (int k = 0; k < NSLOT; k++) syy[k] = make_float2(0.f, 0.f);

    // ================= channel loop =================
    #pragma unroll 1
    for (int c = 0; c < CCH; c++) {
        __syncthreads();
        // stage y halo for this channel (accumulate sum(y^2) for free)
        #pragma unroll
        for (int k = 0; k < NSLOT; k++) {
            if (mask & (1u << k)) {
                float2 v = make_float2(0.f, 0.f);
                if (mask & (0x100u << k)) v = __ldg(yp + g2of[k]);
                reinterpret_cast<float2*>(sy)[tid + k * NTHREADS] = v;
                syy[k].x = fmaf(v.x, v.x, syy[k].x);
                syy[k].y = fmaf(v.y, v.y, syy[k].y);
            }
        }
        __syncthreads();

        const float4 xv = __ldg(xp);
        xp += PLANE / 4;
        yp += PLANE / 2;
        sxx[0] = fmaf(xv.x, xv.x, sxx[0]);
        sxx[1] = fmaf(xv.y, xv.y, sxx[1]);
        sxx[2] = fmaf(xv.z, xv.z, sxx[2]);
        sxx[3] = fmaf(xv.w, xv.w, sxx[3]);

        #pragma unroll
        for (int i = 0; i < 7; i++) {
            const float* row = &sy[(ty + i) * SMW + tx * 4];
            float4 t0 = *reinterpret_cast<const float4*>(row);
            float4 t1 = *reinterpret_cast<const float4*>(row + 4);
            float4 t2 = *reinterpret_cast<const float4*>(row + 8);
            float yr[12];
            yr[0] = t0.x; yr[1]  = t0.y; yr[2]  = t0.z; yr[3]  = t0.w;
            yr[4] = t1.x; yr[5]  = t1.y; yr[6]  = t1.z; yr[7]  = t1.w;
            yr[8] = t2.x; yr[9]  = t2.y; yr[10] = t2.z; yr[11] = t2.w;
            // pixel p at offset j reads smem col (4tx + p + j + 1) -> yr[p+j+1]
            #pragma unroll
            for (int j = 0; j < 7; j++) {
                acc[i * 7 + j][0] = fmaf(xv.x, yr[j + 1], acc[i * 7 + j][0]);
                acc[i * 7 + j][1] = fmaf(xv.y, yr[j + 2], acc[i * 7 + j][1]);
                acc[i * 7 + j][2] = fmaf(xv.z, yr[j + 3], acc[i * 7 + j][2]);
                acc[i * 7 + j][3] = fmaf(xv.w, yr[j + 4], acc[i * 7 + j][3]);
            }
        }
    }

    // ================= epilogue: normalize =================
    __syncthreads();
    #pragma unroll
    for (int k = 0; k < NSLOT; k++)
        if (mask & (1u << k))
            reinterpret_cast<float2*>(sy)[tid + k * NTHREADS] = syy[k];
    __syncthreads();

    float invx[4];
    #pragma unroll
    for (int p = 0; p < 4; p++)
        invx[p] = 1.0f / fmaxf(sqrtf(sxx[p]), EPSF);

    float* op = out + (((size_t)b * 49) * HH + h) * WW + w0 + tx * 4;
    #pragma unroll
    for (int i = 0; i < 7; i++) {
        const float* row = &sy[(ty + i) * SMW + tx * 4];
        float inr[11];
        #pragma unroll
        for (int t = 1; t <= 10; t++)
            inr[t] = 1.0f / fmaxf(sqrtf(row[t]), EPSF);
        #pragma unroll
        for (int j = 0; j < 7; j++) {
            float4 o4;
            o4.x = acc[i * 7 + j][0] * invx[0] * inr[j + 1];
            o4.y = acc[i * 7 + j][1] * invx[1] * inr[j + 2];
            o4.z = acc[i * 7 + j][2] * invx[2] * inr[j + 3];
            o4.w = acc[i * 7 + j][3] * invx[3] * inr[j + 4];
            *reinterpret_cast<float4*>(op + (size_t)(i * 7 + j) * PLANE) = o4;
        }
    }
}

extern "C" void kernel_launch(void* const* d_in, const int* in_sizes, int n_in,
                              void* d_out, int out_size) {
    const float* x = (const float*)d_in[0];
    const float* y = (const float*)d_in[1];
    float* out = (float*)d_out;
    int B = in_sizes[0] / (CCH * HH * WW);   // = 4
    dim3 grid(WW / TW, HH / TH, B);
    corr_kernel<<<grid, NTHREADS>>>(x, y, out);
}